// round 4
// baseline (speedup 1.0000x reference)
#include <cuda_runtime.h>
#include <cstdint>

#define T_    256
#define N_    4096
#define C_    12
#define D_    256
#define K_    12
#define KPAD  136          // 272/2 k-pairs: 128 h + 6 x/onehot + 2 pad
#define RB    32
#define NTHR  256
#define NBLK  (N_ / RB)    // 128
#define CH    17           // k-pairs per chunk; 4 chunks per K-half
#define CHW   (CH * D_)    // ull per chunk buffer (4352)
#define CHBYTES (CHW * 8)  // 34816

typedef unsigned long long ull;

// ---- smem layout (ull units) ----
#define U_W    0                       // 4 chunk buffers (A0,A1,B0,B1)
#define U_SH   (U_W + 4 * CHW)         // h_aug [136][32] ull
#define U_WY   (U_SH + KPAD * RB)      // Wy paired [12][128] ull
#define U_BE   (U_WY + 12 * 128)       // enc bias {b,0} [256]
#define U_BD   (U_BE + 256)            // dec bias {b,0} [256]
#define U_PB   (U_BD + 256)            // B partials: 8192 floats (4096 ull)
#define U_YT   (U_PB + 4096)           // ytmp 384 floats
#define U_BY   (U_YT + 192)            // by 12 floats (pad 16)
#define U_MB   (U_BY + 8)              // 4 mbarriers
#define U_TOT  (U_MB + 4)
#define SMEM_BYTES (U_TOT * 8)         // 224,864 B

// W pre-paired: g_Wp[phase][kp][d] = {W(d,2kp), W(d,2kp+1)}; kp>=128 -> Wx cols; kp>=134 -> 0
__device__ float2 g_Wp[2][KPAD][D_];

__device__ __forceinline__ void ffma2(ull &d, ull a, ull b) {
    asm("fma.rn.f32x2 %0, %1, %2, %0;" : "+l"(d) : "l"(a), "l"(b));
}
__device__ __forceinline__ void unpack2(ull v, float &lo, float &hi) {
    asm("mov.b64 {%0, %1}, %2;" : "=f"(lo), "=f"(hi) : "l"(v));
}
__device__ __forceinline__ ull pk(float a, float b) {
    ull r; asm("mov.b64 %0, {%1, %2};" : "=l"(r) : "f"(a), "f"(b)); return r;
}
__device__ __forceinline__ unsigned smem_u32(const void* p) {
    unsigned r;
    asm("{ .reg .u64 t; cvta.to.shared.u64 t, %1; cvt.u32.u64 %0, t; }" : "=r"(r) : "l"(p));
    return r;
}
__device__ __forceinline__ void mbar_init(unsigned mb, unsigned cnt) {
    asm volatile("mbarrier.init.shared.b64 [%0], %1;" :: "r"(mb), "r"(cnt) : "memory");
}
__device__ __forceinline__ void mbar_wait(unsigned mb, unsigned parity) {
    unsigned done;
    asm volatile("{\n\t.reg .pred p;\n\t"
                 "mbarrier.try_wait.parity.acquire.cta.shared::cta.b64 p, [%1], %2;\n\t"
                 "selp.b32 %0, 1, 0, p;\n\t}"
                 : "=r"(done) : "r"(mb), "r"(parity) : "memory");
    if (!done) {
        asm volatile("{\n\t.reg .pred P;\n"
                     "W%=:\n\t"
                     "mbarrier.try_wait.parity.acquire.cta.shared::cta.b64 P, [%0], %1, 0x989680;\n\t"
                     "@P bra.uni D%=;\n\t"
                     "bra.uni W%=;\n"
                     "D%=:\n\t}"
                     :: "r"(mb), "r"(parity) : "memory");
    }
}
__device__ __forceinline__ void tma_issue(unsigned mb, unsigned dst, const void* src) {
    asm volatile("mbarrier.arrive.expect_tx.shared.b64 _, [%0], %1;"
                 :: "r"(mb), "r"((unsigned)CHBYTES) : "memory");
    asm volatile("cp.async.bulk.shared::cluster.global.mbarrier::complete_tx::bytes "
                 "[%0], [%1], %2, [%3];"
                 :: "r"(dst), "l"(src), "r"((unsigned)CHBYTES), "r"(mb) : "memory");
}
__device__ __forceinline__ void barset(int id) {
    asm volatile("bar.sync %0, 128;" :: "r"(id) : "memory");
}

// ---------------- prep: paired fused weight image ----------------
__global__ void prep_kernel(const float* __restrict__ eWh, const float* __restrict__ eWx,
                            const float* __restrict__ dWh, const float* __restrict__ dWx)
{
    int p  = blockIdx.x / KPAD;
    int kp = blockIdx.x % KPAD;
    int d  = threadIdx.x;
    const float* Wh = p ? dWh : eWh;
    const float* Wx = p ? dWx : eWx;
    int k0 = 2 * kp, k1 = 2 * kp + 1;
    float v0 = (k0 < D_) ? Wh[d * D_ + k0] : ((k0 < D_ + C_) ? Wx[d * C_ + (k0 - D_)] : 0.f);
    float v1 = (k1 < D_) ? Wh[d * D_ + k1] : ((k1 < D_ + C_) ? Wx[d * C_ + (k1 - D_)] : 0.f);
    g_Wp[p][kp][d] = make_float2(v0, v1);
}

// ---------------- main persistent kernel ----------------
extern "C" __global__ void __launch_bounds__(NTHR, 1)
seq2seq_kernel(const float* __restrict__ x,
               const float* __restrict__ ebx, const float* __restrict__ dbx,
               const float* __restrict__ dWy, const float* __restrict__ dby,
               float* __restrict__ out)
{
    extern __shared__ ull smu[];
    ull*   smW  = smu + U_W;
    ull*   sh   = smu + U_SH;
    ull*   sWy  = smu + U_WY;
    ull*   sbe  = smu + U_BE;
    ull*   sbd  = smu + U_BD;
    float* pb   = (float*)(smu + U_PB);
    float* yt   = (float*)(smu + U_YT);
    float* sby  = (float*)(smu + U_BY);

    const int tid = threadIdx.x;
    const int isB = tid >> 7;            // warps 0-3 = set A, 4-7 = set B
    const int sid = tid & 127;
    const int r0  = (sid & 3) * 8;       // 8 rows
    const int d0  = (sid >> 2) * 8;      // 8 output-pairs (ull units)
    const int kp0 = isB ? 68 : 0;
    const int setb2 = isB * 2;           // buffer base (0 or 2)
    const int barid = 1 + isB;
    const bool elected = (tid == (isB ? 128 : 0));
    const int rowbase = blockIdx.x * RB;

    const unsigned sW_u32 = smem_u32(smu) + U_W * 8;
    const unsigned mb_u32 = smem_u32(smu) + U_MB * 8;

    const int c1 = sid >> 5;             // x staging: pair-col (first slot)
    const int r1 = sid & 31;

    // ---- init ----
    for (int i = tid; i < KPAD * RB; i += NTHR) sh[i] = 0ull;
    for (int i = tid; i < 12 * 128; i += NTHR)  sWy[i] = ((const ull*)dWy)[i];
    sbe[tid] = pk(ebx[tid], 0.f);
    sbd[tid] = pk(dbx[tid], 0.f);
    if (tid < K_) sby[tid] = dby[tid];
    if (tid == 0)
        for (int m = 0; m < 4; ++m) mbar_init(mb_u32 + m * 8, 1);
    __syncthreads();

    // stage x_0 into aug rows (set B threads: 192 slots)
    if (isB) {
        const float2 a = *(const float2*)(x + ((size_t)rowbase + r1) * C_ + 2 * c1);
        sh[(128 + c1) * RB + r1] = pk(a.x, a.y);
        if (sid < 64) {
            const float2 b = *(const float2*)(x + ((size_t)rowbase + r1) * C_ + 2 * (4 + c1));
            sh[(132 + c1) * RB + r1] = pk(b.x, b.y);
        }
    }
    // prime chunks 0,1 per set
    if (tid == 0) {
        tma_issue(mb_u32 + 0, sW_u32 + 0 * CHBYTES, (const char*)g_Wp);
        tma_issue(mb_u32 + 8, sW_u32 + 1 * CHBYTES, (const char*)g_Wp + (size_t)CH * D_ * 8);
    }
    if (tid == 128) {
        tma_issue(mb_u32 + 16, sW_u32 + 2 * CHBYTES, (const char*)g_Wp + (size_t)68 * D_ * 8);
        tma_issue(mb_u32 + 24, sW_u32 + 3 * CHBYTES, (const char*)g_Wp + (size_t)85 * D_ * 8);
    }
    __syncthreads();

    int par[2] = {0, 0};
    ull acc[64];

    for (int t = 0; t < 2 * T_; ++t) {
        const bool dec = (t >= T_);

        // prefetch next x slice (set B) into regs
        ull xv1 = 0ull, xv2 = 0ull;
        if (!dec && (t + 1) < T_ && isB) {
            const float2 a = *(const float2*)(x + ((size_t)(t + 1) * N_ + rowbase + r1) * C_ + 2 * c1);
            xv1 = pk(a.x, a.y);
            if (sid < 64) {
                const float2 b = *(const float2*)(x + ((size_t)(t + 1) * N_ + rowbase + r1) * C_ + 2 * (4 + c1));
                xv2 = pk(b.x, b.y);
            }
        }

        // acc init: A gets bias {b,0}; B gets zero
        if (!isB) {
            const ulonglong2* bp = (const ulonglong2*)((dec ? sbd : sbe) + d0);
            ulonglong2 b01 = bp[0], b23 = bp[1], b45 = bp[2], b67 = bp[3];
            ull bj[8] = {b01.x, b01.y, b23.x, b23.y, b45.x, b45.y, b67.x, b67.y};
            #pragma unroll
            for (int i = 0; i < 8; ++i)
                #pragma unroll
                for (int j = 0; j < 8; ++j) acc[i * 8 + j] = bj[j];
        } else {
            #pragma unroll
            for (int m = 0; m < 64; ++m) acc[m] = 0ull;
        }

        // ---- GEMM: 4 chunks over this set's K-half ----
        #pragma unroll 1
        for (int c = 0; c < 4; ++c) {
            const int bsel = c & 1;
            const int buf  = setb2 + bsel;
            mbar_wait(mb_u32 + buf * 8, par[bsel]); par[bsel] ^= 1;

            const ull* wchunk = smW + (size_t)buf * CHW + d0;
            const ull* hb     = sh + (size_t)(kp0 + c * CH) * RB + r0;

            #pragma unroll 2
            for (int kk = 0; kk < CH; ++kk) {
                const ulonglong2* hp = (const ulonglong2*)(hb + (size_t)kk * RB);
                ulonglong2 h01 = hp[0], h23 = hp[1], h45 = hp[2], h67 = hp[3];
                const ulonglong2* wp = (const ulonglong2*)(wchunk + (size_t)kk * D_);
                ulonglong2 w01 = wp[0], w23 = wp[1], w45 = wp[2], w67 = wp[3];
                ull hr[8] = {h01.x, h01.y, h23.x, h23.y, h45.x, h45.y, h67.x, h67.y};
                ull wr[8] = {w01.x, w01.y, w23.x, w23.y, w45.x, w45.y, w67.x, w67.y};
                #pragma unroll
                for (int i = 0; i < 8; ++i)
                    #pragma unroll
                    for (int j = 0; j < 8; ++j)
                        ffma2(acc[i * 8 + j], hr[i], wr[j]);
            }
            barset(barid);   // set-local: buffer consumed by all set threads

            if (elected) {
                int cc = c + 2;
                int tt = t + (cc >> 2);
                cc &= 3;
                if (tt < 2 * T_) {
                    int ph = (tt >= T_) ? 1 : 0;
                    tma_issue(mb_u32 + (setb2 + (cc & 1)) * 8,
                              sW_u32 + (setb2 + (cc & 1)) * CHBYTES,
                              (const char*)g_Wp + ((size_t)ph * KPAD + kp0 + cc * CH) * D_ * 8);
                }
            }
        }

        // ---- B: collapse partials, stage aug; then S1 ----
        if (isB) {
            float4* pw = (float4*)(pb + sid * 64);
            #pragma unroll
            for (int q = 0; q < 16; ++q) {
                float a0, b0, a1, b1, a2, b2, a3, b3;
                unpack2(acc[4 * q + 0], a0, b0);
                unpack2(acc[4 * q + 1], a1, b1);
                unpack2(acc[4 * q + 2], a2, b2);
                unpack2(acc[4 * q + 3], a3, b3);
                pw[q] = make_float4(a0 + b0, a1 + b1, a2 + b2, a3 + b3);
            }
            if (!dec) {  // stage x_{t+1} or SOS (pair-col 5 = {1,0})
                if (t + 1 < T_) {
                    sh[(128 + c1) * RB + r1] = xv1;
                    if (sid < 64) sh[(132 + c1) * RB + r1] = xv2;
                } else {
                    sh[(128 + c1) * RB + r1] = 0ull;
                    if (sid < 64) sh[(132 + c1) * RB + r1] = (c1 == 1) ? pk(1.f, 0.f) : 0ull;
                }
            }
        }
        __syncthreads();   // S1: partials + aug visible; all sh GEMM reads done

        // ---- A: reduce + relu + write paired h ----
        if (!isB) {
            float f[64];
            const float4* pr = (const float4*)(pb + sid * 64);
            #pragma unroll
            for (int q = 0; q < 16; ++q) {
                float4 v = pr[q];
                float lo, hi;
                unpack2(acc[4 * q + 0], lo, hi); f[4 * q + 0] = fmaxf(lo + hi + v.x, 0.f);
                unpack2(acc[4 * q + 1], lo, hi); f[4 * q + 1] = fmaxf(lo + hi + v.y, 0.f);
                unpack2(acc[4 * q + 2], lo, hi); f[4 * q + 2] = fmaxf(lo + hi + v.z, 0.f);
                unpack2(acc[4 * q + 3], lo, hi); f[4 * q + 3] = fmaxf(lo + hi + v.w, 0.f);
            }
            #pragma unroll
            for (int jp = 0; jp < 4; ++jp) {
                float4* dst = (float4*)(sh + (size_t)((d0 >> 1) + jp) * RB + r0);
                #pragma unroll
                for (int i2 = 0; i2 < 4; ++i2)
                    dst[i2] = make_float4(f[(2 * i2) * 8 + 2 * jp],     f[(2 * i2) * 8 + 2 * jp + 1],
                                          f[(2 * i2 + 1) * 8 + 2 * jp], f[(2 * i2 + 1) * 8 + 2 * jp + 1]);
            }
        }
        __syncthreads();   // S2: new h visible

        // ---- decoder: set B computes y/argmax/feedback; set A races ahead ----
        if (dec && isB) {
            #pragma unroll
            for (int j = 0; j < 3; ++j) {
                int task = sid + 128 * j;
                int r = task & 31, k = task >> 5;
                ull a = 0ull;
                const ull* hc = sh + r;
                const ull* wk = sWy + (size_t)k * 128;
                #pragma unroll 8
                for (int m = 0; m < 128; ++m) ffma2(a, hc[(size_t)m * RB], wk[m]);
                float lo, hi; unpack2(a, lo, hi);
                yt[r * 12 + k] = lo + hi + sby[k];
            }
            barset(2);
            // zero aug rows (pair-cols 0..5)
            sh[(128 + c1) * RB + r1] = 0ull;
            if (sid < 64) sh[(132 + c1) * RB + r1] = 0ull;
            barset(2);
            if (sid < 32) {   // warp 4: argmax + output + one-hot feedback
                const float* yr = yt + sid * 12;
                float v[12];
                #pragma unroll
                for (int q = 0; q < 3; ++q) {
                    float4 fv = *(const float4*)(yr + 4 * q);
                    v[4 * q] = fv.x; v[4 * q + 1] = fv.y; v[4 * q + 2] = fv.z; v[4 * q + 3] = fv.w;
                }
                float best = v[0]; int sel = 0;
                #pragma unroll
                for (int q = 1; q < 12; ++q)
                    if (v[q] > best) { best = v[q]; sel = q; }
                float* og = out + ((size_t)(t - T_) * N_ + rowbase + sid) * K_;
                *(float4*)(og)     = make_float4(v[0], v[1], v[2],  v[3]);
                *(float4*)(og + 4) = make_float4(v[4], v[5], v[6],  v[7]);
                *(float4*)(og + 8) = make_float4(v[8], v[9], v[10], v[11]);
                sh[(128 + (sel >> 1)) * RB + sid] = (sel & 1) ? pk(0.f, 1.f) : pk(1.f, 0.f);
            }
            barset(2);
        }
    }
}

extern "C" void kernel_launch(void* const* d_in, const int* in_sizes, int n_in,
                              void* d_out, int out_size) {
    const float* x   = (const float*)d_in[0];
    const float* eWx = (const float*)d_in[1];
    const float* ebx = (const float*)d_in[2];
    const float* eWh = (const float*)d_in[3];
    const float* dWx = (const float*)d_in[6];
    const float* dbx = (const float*)d_in[7];
    const float* dWh = (const float*)d_in[8];
    const float* dWy = (const float*)d_in[9];
    const float* dby = (const float*)d_in[10];

    prep_kernel<<<2 * KPAD, D_>>>(eWh, eWx, dWh, dWx);

    cudaFuncSetAttribute(seq2seq_kernel,
                         cudaFuncAttributeMaxDynamicSharedMemorySize, SMEM_BYTES);
    seq2seq_kernel<<<NBLK, NTHR, SMEM_BYTES>>>(
        x, ebx, dbx, dWy, dby, (float*)d_out);
}